// round 3
// baseline (speedup 1.0000x reference)
#include <cuda_runtime.h>

#define NN 4096
#define CC 128
#define NC (NN*CC)

// Scratch (device globals: allocation-free per harness rules)
__device__ float    g_qkv[3*NC];   // q | k | v, each [N][C]
__device__ float    g_attn[NC];    // attention output before out-proj
__device__ float    g_y[NC];       // pre-layernorm (residual added)
__device__ unsigned g_mask[NC];    // 4096x4096 adjacency bitmask (N*N/32 == N*C words)
__device__ unsigned g_odd_or;      // edge-index dtype detection flag

// ---------------------------------------------------------------------------
// 1) adjacency bitmask + dtype detection
// ---------------------------------------------------------------------------
__global__ void clear_mask_kernel() {
    int i = blockIdx.x * blockDim.x + threadIdx.x;
    if (i == 0) g_odd_or = 0u;
    int stride = gridDim.x * blockDim.x;
    for (; i < NC; i += stride) g_mask[i] = 0u;
}

// OR-reduce words at odd positions among the first n2 32-bit words.
// int64 edge_index (values < 2^31) -> all odd words are zero high-halves -> OR==0.
// int32 edge_index -> odd words are real indices -> OR!=0 (prob ~1).
__global__ void detect_kernel(const unsigned* __restrict__ w, int n2) {
    unsigned v = 0;
    for (int i = blockIdx.x * blockDim.x + threadIdx.x; i < (n2 >> 1);
         i += gridDim.x * blockDim.x)
        v |= w[2 * i + 1];
    #pragma unroll
    for (int o = 16; o; o >>= 1) v |= __shfl_xor_sync(0xffffffffu, v, o);
    if ((threadIdx.x & 31) == 0 && v) atomicOr(&g_odd_or, v);
}

__global__ void scatter_kernel(const void* __restrict__ ei_raw, int E) {
    int e = blockIdx.x * blockDim.x + threadIdx.x;
    if (e >= E) return;
    int r, c;
    if (g_odd_or == 0u) {  // int64 layout
        const long long* ei = (const long long*)ei_raw;
        r = (int)ei[e];
        c = (int)ei[E + e];
    } else {               // int32 layout
        const int* ei = (const int*)ei_raw;
        r = ei[e];
        c = ei[E + e];
    }
    if ((unsigned)r < NN && (unsigned)c < NN)
        atomicOr(&g_mask[(r << 7) + (c >> 5)], 1u << (c & 31));
}

// ---------------------------------------------------------------------------
// 2) fp32 GEMM: out[n][c] = sum_k A[n][k] * W[c][k] + bias[c] (+ res[n][c])
//    BM=32 rows, BN=128 cols (full), BK=32, 256 threads, 4x4 register tile
// ---------------------------------------------------------------------------
__device__ __forceinline__ void gemm_body(const float* __restrict__ A,
                                          const float* __restrict__ W,
                                          const float* __restrict__ bias,
                                          const float* __restrict__ res,
                                          float* __restrict__ out) {
    __shared__ float As[32][33];    // [kk][m]  stride 33 -> conflict-free
    __shared__ float Bs[32][132];   // [kk][c]  stride 132 (33 float4s) -> aligned
    const int n0 = blockIdx.x * 32;
    const int t  = threadIdx.x;
    const int tn = t & 31;          // col group: cols tn*4 .. tn*4+3
    const int tm = t >> 5;          // row group: rows tm*4 .. tm*4+3
    const int kk = t & 31;          // loader: k index (coalesced)
    const int rr = t >> 5;          // loader: row/col index base
    float acc[4][4] = {};

    for (int k0 = 0; k0 < CC; k0 += 32) {
        #pragma unroll
        for (int p = 0; p < 4; p++)
            As[kk][rr + p*8] = A[(n0 + rr + p*8)*CC + k0 + kk];
        #pragma unroll
        for (int p = 0; p < 16; p++)
            Bs[kk][rr + p*8] = W[(rr + p*8)*CC + k0 + kk];
        __syncthreads();
        #pragma unroll
        for (int q = 0; q < 32; q++) {
            float4 b4 = *(const float4*)&Bs[q][tn*4];
            float a0 = As[q][tm*4+0];
            float a1 = As[q][tm*4+1];
            float a2 = As[q][tm*4+2];
            float a3 = As[q][tm*4+3];
            acc[0][0] += a0*b4.x; acc[0][1] += a0*b4.y; acc[0][2] += a0*b4.z; acc[0][3] += a0*b4.w;
            acc[1][0] += a1*b4.x; acc[1][1] += a1*b4.y; acc[1][2] += a1*b4.z; acc[1][3] += a1*b4.w;
            acc[2][0] += a2*b4.x; acc[2][1] += a2*b4.y; acc[2][2] += a2*b4.z; acc[2][3] += a2*b4.w;
            acc[3][0] += a3*b4.x; acc[3][1] += a3*b4.y; acc[3][2] += a3*b4.z; acc[3][3] += a3*b4.w;
        }
        __syncthreads();
    }

    float4 bb = *(const float4*)&bias[tn*4];
    #pragma unroll
    for (int i = 0; i < 4; i++) {
        int row = n0 + tm*4 + i;
        float4 o;
        o.x = acc[i][0] + bb.x;
        o.y = acc[i][1] + bb.y;
        o.z = acc[i][2] + bb.z;
        o.w = acc[i][3] + bb.w;
        if (res) {
            float4 r4 = *(const float4*)&res[row*CC + tn*4];
            o.x += r4.x; o.y += r4.y; o.z += r4.z; o.w += r4.w;
        }
        *(float4*)&out[row*CC + tn*4] = o;
    }
}

__global__ __launch_bounds__(256) void qkv_gemm_kernel(
        const float* __restrict__ x,
        const float* __restrict__ wq, const float* __restrict__ wk, const float* __restrict__ wv,
        const float* __restrict__ bq, const float* __restrict__ bk, const float* __restrict__ bv) {
    int which = blockIdx.y;
    const float* W = (which == 0) ? wq : (which == 1) ? wk : wv;
    const float* B = (which == 0) ? bq : (which == 1) ? bk : bv;
    gemm_body(x, W, B, nullptr, g_qkv + which * NC);
}

__global__ __launch_bounds__(256) void out_gemm_kernel(
        const float* __restrict__ wo, const float* __restrict__ bo,
        const float* __restrict__ x) {
    gemm_body(g_attn, wo, bo, x, g_y);
}

// ---------------------------------------------------------------------------
// 3) sparse attention: block per node, warp per head, online softmax
// ---------------------------------------------------------------------------
__global__ __launch_bounds__(128) void attn_kernel() {
    __shared__ int nbr[NN];     // worst-case degree
    __shared__ int wsum[4];
    __shared__ int s_deg;
    const int n    = blockIdx.x;
    const int t    = threadIdx.x;      // 0..127
    const int lane = t & 31;
    const int wid  = t >> 5;           // warp == head

    // --- build deduped neighbor list from bitmask row ---
    unsigned w = g_mask[(n << 7) + t];
    int c = __popc(w);
    int inc = c;
    #pragma unroll
    for (int o = 1; o < 32; o <<= 1) {
        int v = __shfl_up_sync(0xffffffffu, inc, o);
        if (lane >= o) inc += v;
    }
    if (lane == 31) wsum[wid] = inc;
    __syncthreads();
    int base = 0;
    for (int i = 0; i < wid; i++) base += wsum[i];
    int off = base + inc - c;          // exclusive offset for this thread
    int colbase = t << 5;
    while (w) {
        int b = __ffs(w) - 1;
        w &= w - 1;
        nbr[off++] = colbase + b;
    }
    if (t == 127) s_deg = off;
    __syncthreads();
    const int deg = s_deg;             // >= 1 (self loops guaranteed)

    // --- online softmax over neighbors, one head per warp, lane = dim ---
    const int h = wid;
    const float qv = g_qkv[n*CC + h*32 + lane] * 0.17677669529663687f; // 1/sqrt(32)
    float M = -1e30f, l = 0.f, acc = 0.f;

    for (int j = 0; j < deg; j++) {
        int m = nbr[j];
        float kv = g_qkv[NC + m*CC + h*32 + lane];
        float s = qv * kv;
        #pragma unroll
        for (int o = 16; o; o >>= 1) s += __shfl_xor_sync(0xffffffffu, s, o);
        float vv = g_qkv[2*NC + m*CC + h*32 + lane];
        float Mn = fmaxf(M, s);
        float corr = __expf(M - Mn);
        float p = __expf(s - Mn);
        l   = l * corr + p;
        acc = acc * corr + p * vv;
        M = Mn;
    }
    g_attn[n*CC + h*32 + lane] = acc / l;
}

// ---------------------------------------------------------------------------
// 4) LayerNorm: warp per row
// ---------------------------------------------------------------------------
__global__ __launch_bounds__(256) void ln_kernel(const float* __restrict__ gamma,
                                                 const float* __restrict__ beta,
                                                 float* __restrict__ out) {
    int warp = (blockIdx.x * blockDim.x + threadIdx.x) >> 5;
    int lane = threadIdx.x & 31;
    if (warp >= NN) return;
    float4 y = *(const float4*)&g_y[warp*CC + lane*4];
    float s  = y.x + y.y + y.z + y.w;
    float s2 = y.x*y.x + y.y*y.y + y.z*y.z + y.w*y.w;
    #pragma unroll
    for (int o = 16; o; o >>= 1) {
        s  += __shfl_xor_sync(0xffffffffu, s,  o);
        s2 += __shfl_xor_sync(0xffffffffu, s2, o);
    }
    float mu  = s * (1.f / CC);
    float var = s2 * (1.f / CC) - mu * mu;
    float rs  = rsqrtf(var + 1e-5f);
    float4 g = *(const float4*)&gamma[lane*4];
    float4 b = *(const float4*)&beta[lane*4];
    float4 o4;
    o4.x = (y.x - mu) * rs * g.x + b.x;
    o4.y = (y.y - mu) * rs * g.y + b.y;
    o4.z = (y.z - mu) * rs * g.z + b.z;
    o4.w = (y.w - mu) * rs * g.w + b.w;
    *(float4*)&out[warp*CC + lane*4] = o4;
}

// ---------------------------------------------------------------------------
extern "C" void kernel_launch(void* const* d_in, const int* in_sizes, int n_in,
                              void* d_out, int out_size) {
    const float* x     = (const float*)d_in[0];
    const void*  ei    = d_in[1];
    const float* wq    = (const float*)d_in[2];
    const float* bq    = (const float*)d_in[3];
    const float* wk    = (const float*)d_in[4];
    const float* bk    = (const float*)d_in[5];
    const float* wv    = (const float*)d_in[6];
    const float* bv    = (const float*)d_in[7];
    const float* wo    = (const float*)d_in[8];
    const float* bo    = (const float*)d_in[9];
    const float* gamma = (const float*)d_in[10];
    const float* beta  = (const float*)d_in[11];
    float*       out   = (float*)d_out;
    const int n_elems = in_sizes[1];   // 2*E regardless of dtype
    const int E = n_elems / 2;

    clear_mask_kernel<<<512, 256>>>();
    detect_kernel<<<256, 256>>>((const unsigned*)ei, n_elems);
    scatter_kernel<<<(E + 255) / 256, 256>>>(ei, E);
    qkv_gemm_kernel<<<dim3(NN/32, 3), 256>>>(x, wq, wk, wv, bq, bk, bv);
    attn_kernel<<<NN, 128>>>();
    out_gemm_kernel<<<NN/32, 256>>>(wo, bo, x);
    ln_kernel<<<NN/8, 256>>>(gamma, beta, out);
}